// round 15
// baseline (speedup 1.0000x reference)
#include <cuda_runtime.h>

#define Bn 32
#define Nn 1024
#define Cn 768
#define C4 192        // Cn / 4
#define ZCHUNK 32
#define ROWS_PER_Z 32 // Nn / ZCHUNK
#define ORBITS 272

__device__ float4 g_pdot[Bn * ZCHUNK];  // per-(b,z) partial dot with W

// Pass 1 (pool + GEMV partial): grid (Bn, ZCHUNK), block 192.
// Pure streaming: block sums its 32 rows, dots with W, writes one float4
// partial, exits. NO atomics, NO tickets, NO finalizer.
__global__ void __launch_bounds__(192) pool_kernel(
    const float* __restrict__ x,
    const float* __restrict__ W) {
    int b = blockIdx.x;
    int z = blockIdx.y;
    int tid = threadIdx.x;  // 0..191
    const float4* p = (const float4*)(x + ((size_t)b * Nn + (size_t)z * ROWS_PER_Z) * Cn) + tid;

    float4 a0 = {0,0,0,0}, a1 = {0,0,0,0}, a2 = {0,0,0,0}, a3 = {0,0,0,0};
#pragma unroll
    for (int n = 0; n < ROWS_PER_Z; n += 8) {
        float4 v[8];
#pragma unroll
        for (int u = 0; u < 8; u++)
            v[u] = __ldcg(&p[(size_t)(n + u) * C4]);
        a0.x += v[0].x + v[4].x; a0.y += v[0].y + v[4].y;
        a0.z += v[0].z + v[4].z; a0.w += v[0].w + v[4].w;
        a1.x += v[1].x + v[5].x; a1.y += v[1].y + v[5].y;
        a1.z += v[1].z + v[5].z; a1.w += v[1].w + v[5].w;
        a2.x += v[2].x + v[6].x; a2.y += v[2].y + v[6].y;
        a2.z += v[2].z + v[6].z; a2.w += v[2].w + v[6].w;
        a3.x += v[3].x + v[7].x; a3.y += v[3].y + v[7].y;
        a3.z += v[3].z + v[7].z; a3.w += v[3].w + v[7].w;
    }
    float4 s;
    s.x = (a0.x + a1.x) + (a2.x + a3.x);
    s.y = (a0.y + a1.y) + (a2.y + a3.y);
    s.z = (a0.z + a1.z) + (a2.z + a3.z);
    s.w = (a0.w + a1.w) + (a2.w + a3.w);

    // per-thread dot with W rows (thread owns channels 4*tid..4*tid+3)
    float d[4];
#pragma unroll
    for (int k = 0; k < 4; k++) {
        float4 w4 = __ldg(&((const float4*)W)[k * C4 + tid]);
        d[k] = s.x * w4.x + s.y * w4.y + s.z * w4.z + s.w * w4.w;
    }
    __shared__ float sdot[6][4];
    int lane = tid & 31, wid = tid >> 5;
#pragma unroll
    for (int k = 0; k < 4; k++) {
#pragma unroll
        for (int off = 16; off > 0; off >>= 1)
            d[k] += __shfl_down_sync(0xffffffffu, d[k], off);
        if (lane == 0) sdot[wid][k] = d[k];
    }
    __syncthreads();
    if (tid < 32) {
        int k = tid & 3, w = tid >> 2;
        float v = (w < 6) ? sdot[w][k] : 0.f;
        v += __shfl_down_sync(0xffffffffu, v, 16);
        v += __shfl_down_sync(0xffffffffu, v, 8);
        v += __shfl_down_sync(0xffffffffu, v, 4);
        if (tid < 4) {
            float* dst = (float*)&g_pdot[(size_t)b * ZCHUNK + z];
            __stcg(&dst[k], v);
        }
    }
}

// Pass 2: orbit merge, batches in REVERSE order (L2 recency from the pool
// pass). Each WARP independently recomputes alpha[b] via one float4 L2 load
// per lane + butterfly shuffles — no shared memory, no __syncthreads, fully
// overlapped with the in-flight x loads. Degenerate orbits skip duplicate
// loads AND stores.
__global__ void __launch_bounds__(192) merge_kernel(
    const float* __restrict__ x,
    const float* __restrict__ bias,
    float* __restrict__ out) {
    int bid = blockIdx.x;
    int b = (Bn - 1) - (bid / ORBITS);   // reverse batch order
    int o = bid % ORBITS;
    int i = 0, cnt = 32;
    while (o >= cnt) { o -= cnt; i++; cnt -= 2; }
    int j = i + o;  // i <= j <= 31-i

    int l   = (i << 5) | j;
    int tl  = (j << 5) | i;
    int rl  = 1023 - l;
    int rtl = 1023 - tl;
    bool d1 = (i == j);        // tl==l,  rtl==rl
    bool d2 = (j == 31 - i);   // rl==tl, rtl==l

    const float4* xb = (const float4*)(x + (size_t)b * Nn * Cn);
    float4*       ob = (float4*)(out + (size_t)b * Nn * Cn);
    int t = threadIdx.x;  // 0..191
    int lane = t & 31;

    // issue data loads first — DRAM latency hides the alpha butterfly below
    float4 v0 = __ldcg(&xb[(size_t)l * C4 + t]);
    float4 v1 = d1 ? v0 : __ldcg(&xb[(size_t)tl * C4 + t]);
    float4 v2 = d2 ? v1 : __ldcg(&xb[(size_t)rl * C4 + t]);
    float4 v3 = d1 ? v2 : (d2 ? v0 : __ldcg(&xb[(size_t)rtl * C4 + t]));

    // per-warp alpha: lane z holds pdot[b][z]; butterfly-sum all 4 components
    float4 a = __ldg(&g_pdot[(size_t)b * ZCHUNK + lane]);
#pragma unroll
    for (int off = 16; off > 0; off >>= 1) {
        a.x += __shfl_xor_sync(0xffffffffu, a.x, off);
        a.y += __shfl_xor_sync(0xffffffffu, a.y, off);
        a.z += __shfl_xor_sync(0xffffffffu, a.z, off);
        a.w += __shfl_xor_sync(0xffffffffu, a.w, off);
    }
    float c0 = fmaf(a.x, 1.0f / 1024.0f, __ldg(&bias[0]));
    float c1 = fmaf(a.y, 1.0f / 1024.0f, __ldg(&bias[1]));
    float c2 = fmaf(a.z, 1.0f / 1024.0f, __ldg(&bias[2]));
    float c3 = fmaf(a.w, 1.0f / 1024.0f, __ldg(&bias[3]));

    float4 w;
    // out[l] = c0 v0 + c1 v1 + c2 v2 + c3 v3
    w.x = fmaf(c0, v0.x, fmaf(c1, v1.x, fmaf(c2, v2.x, c3 * v3.x)));
    w.y = fmaf(c0, v0.y, fmaf(c1, v1.y, fmaf(c2, v2.y, c3 * v3.y)));
    w.z = fmaf(c0, v0.z, fmaf(c1, v1.z, fmaf(c2, v2.z, c3 * v3.z)));
    w.w = fmaf(c0, v0.w, fmaf(c1, v1.w, fmaf(c2, v2.w, c3 * v3.w)));
    __stcs(&ob[(size_t)l * C4 + t], w);

    if (!d1) {  // out[tl] = c0 v1 + c1 v0 + c2 v3 + c3 v2
        w.x = fmaf(c0, v1.x, fmaf(c1, v0.x, fmaf(c2, v3.x, c3 * v2.x)));
        w.y = fmaf(c0, v1.y, fmaf(c1, v0.y, fmaf(c2, v3.y, c3 * v2.y)));
        w.z = fmaf(c0, v1.z, fmaf(c1, v0.z, fmaf(c2, v3.z, c3 * v2.z)));
        w.w = fmaf(c0, v1.w, fmaf(c1, v0.w, fmaf(c2, v3.w, c3 * v2.w)));
        __stcs(&ob[(size_t)tl * C4 + t], w);
    }
    if (!d2) {  // out[rl] = c0 v2 + c1 v3 + c2 v0 + c3 v1
        w.x = fmaf(c0, v2.x, fmaf(c1, v3.x, fmaf(c2, v0.x, c3 * v1.x)));
        w.y = fmaf(c0, v2.y, fmaf(c1, v3.y, fmaf(c2, v0.y, c3 * v1.y)));
        w.z = fmaf(c0, v2.z, fmaf(c1, v3.z, fmaf(c2, v0.z, c3 * v1.z)));
        w.w = fmaf(c0, v2.w, fmaf(c1, v3.w, fmaf(c2, v0.w, c3 * v1.w)));
        __stcs(&ob[(size_t)rl * C4 + t], w);
    }
    if (!d1 && !d2) {  // out[rtl] = c0 v3 + c1 v2 + c2 v1 + c3 v0
        w.x = fmaf(c0, v3.x, fmaf(c1, v2.x, fmaf(c2, v1.x, c3 * v0.x)));
        w.y = fmaf(c0, v3.y, fmaf(c1, v2.y, fmaf(c2, v1.y, c3 * v0.y)));
        w.z = fmaf(c0, v3.z, fmaf(c1, v2.z, fmaf(c2, v1.z, c3 * v0.z)));
        w.w = fmaf(c0, v3.w, fmaf(c1, v2.w, fmaf(c2, v1.w, c3 * v0.w)));
        __stcs(&ob[(size_t)rtl * C4 + t], w);
    }
}

extern "C" void kernel_launch(void* const* d_in, const int* in_sizes, int n_in,
                              void* d_out, int out_size) {
    const float* x    = (const float*)d_in[0];  // (32,1024,768)
    const float* W    = (const float*)d_in[1];  // (4,768)
    const float* bias = (const float*)d_in[2];  // (4,)
    float* out = (float*)d_out;

    dim3 g1(Bn, ZCHUNK);
    pool_kernel<<<g1, 192>>>(x, W);
    merge_kernel<<<Bn * ORBITS, 192>>>(x, bias, out);
}

// round 16
// speedup vs baseline: 1.0370x; 1.0370x over previous
#include <cuda_runtime.h>

#define Bn 32
#define Nn 1024
#define Cn 768
#define C4 192        // Cn / 4
#define ZCHUNK 32
#define ROWS_PER_Z 32 // Nn / ZCHUNK
#define ORBITS 272

__device__ float4 g_pdot[Bn * ZCHUNK];  // per-(b,z) partial dot with W

// Pass 1 (pool + GEMV partial): grid (Bn, ZCHUNK), block 192.
// Pure streaming, no atomics. Each block's LAST action is the PDL signal.
__global__ void __launch_bounds__(192) pool_kernel(
    const float* __restrict__ x,
    const float* __restrict__ W) {
    int b = blockIdx.x;
    int z = blockIdx.y;
    int tid = threadIdx.x;  // 0..191
    const float4* p = (const float4*)(x + ((size_t)b * Nn + (size_t)z * ROWS_PER_Z) * Cn) + tid;

    float4 a0 = {0,0,0,0}, a1 = {0,0,0,0}, a2 = {0,0,0,0}, a3 = {0,0,0,0};
#pragma unroll
    for (int n = 0; n < ROWS_PER_Z; n += 8) {
        float4 v[8];
#pragma unroll
        for (int u = 0; u < 8; u++)
            v[u] = __ldcg(&p[(size_t)(n + u) * C4]);
        a0.x += v[0].x + v[4].x; a0.y += v[0].y + v[4].y;
        a0.z += v[0].z + v[4].z; a0.w += v[0].w + v[4].w;
        a1.x += v[1].x + v[5].x; a1.y += v[1].y + v[5].y;
        a1.z += v[1].z + v[5].z; a1.w += v[1].w + v[5].w;
        a2.x += v[2].x + v[6].x; a2.y += v[2].y + v[6].y;
        a2.z += v[2].z + v[6].z; a2.w += v[2].w + v[6].w;
        a3.x += v[3].x + v[7].x; a3.y += v[3].y + v[7].y;
        a3.z += v[3].z + v[7].z; a3.w += v[3].w + v[7].w;
    }
    float4 s;
    s.x = (a0.x + a1.x) + (a2.x + a3.x);
    s.y = (a0.y + a1.y) + (a2.y + a3.y);
    s.z = (a0.z + a1.z) + (a2.z + a3.z);
    s.w = (a0.w + a1.w) + (a2.w + a3.w);

    // per-thread dot with W rows (thread owns channels 4*tid..4*tid+3)
    float d[4];
#pragma unroll
    for (int k = 0; k < 4; k++) {
        float4 w4 = __ldg(&((const float4*)W)[k * C4 + tid]);
        d[k] = s.x * w4.x + s.y * w4.y + s.z * w4.z + s.w * w4.w;
    }
    __shared__ float sdot[6][4];
    int lane = tid & 31, wid = tid >> 5;
#pragma unroll
    for (int k = 0; k < 4; k++) {
#pragma unroll
        for (int off = 16; off > 0; off >>= 1)
            d[k] += __shfl_down_sync(0xffffffffu, d[k], off);
        if (lane == 0) sdot[wid][k] = d[k];
    }
    __syncthreads();
    if (tid < 32) {
        int k = tid & 3, w = tid >> 2;
        float v = (w < 6) ? sdot[w][k] : 0.f;
        v += __shfl_down_sync(0xffffffffu, v, 16);
        v += __shfl_down_sync(0xffffffffu, v, 8);
        v += __shfl_down_sync(0xffffffffu, v, 4);
        if (tid < 4) {
            float* dst = (float*)&g_pdot[(size_t)b * ZCHUNK + z];
            __stcg(&dst[k], v);
        }
    }
    // signal PDL only after this block's partial is stored
    asm volatile("griddepcontrol.launch_dependents;");
}

// Pass 2: orbit merge, batches in REVERSE order. PDL wait FIRST (no loads
// issued while parked — R9's failure mode avoided). Then warp 0 issues the
// pdot load, all warps issue x loads, the alpha butterfly runs inside the
// x-load DRAM shadow, one barrier joins. Degenerate orbits skip duplicate
// loads AND stores.
__global__ void __launch_bounds__(192) merge_kernel(
    const float* __restrict__ x,
    const float* __restrict__ bias,
    float* __restrict__ out) {
    // park BEFORE doing anything — releases when the pool grid completes
    asm volatile("griddepcontrol.wait;");

    int bid = blockIdx.x;
    int b = (Bn - 1) - (bid / ORBITS);   // reverse batch order
    int o = bid % ORBITS;
    int i = 0, cnt = 32;
    while (o >= cnt) { o -= cnt; i++; cnt -= 2; }
    int j = i + o;  // i <= j <= 31-i

    int l   = (i << 5) | j;
    int tl  = (j << 5) | i;
    int rl  = 1023 - l;
    int rtl = 1023 - tl;
    bool d1 = (i == j);        // tl==l,  rtl==rl
    bool d2 = (j == 31 - i);   // rl==tl, rtl==l

    const float4* xb = (const float4*)(x + (size_t)b * Nn * Cn);
    float4*       ob = (float4*)(out + (size_t)b * Nn * Cn);
    int t = threadIdx.x;  // 0..191
    int lane = t & 31, wid = t >> 5;

    // warp 0 starts the alpha fetch first (L2 hit, ~230 cyc)
    float4 a = {0.f, 0.f, 0.f, 0.f};
    if (wid == 0)
        a = __ldg(&g_pdot[(size_t)b * ZCHUNK + lane]);

    // all warps issue x loads (DRAM, ~600 cyc) — the butterfly below runs
    // in this shadow
    float4 v0 = __ldcg(&xb[(size_t)l * C4 + t]);
    float4 v1 = d1 ? v0 : __ldcg(&xb[(size_t)tl * C4 + t]);
    float4 v2 = d2 ? v1 : __ldcg(&xb[(size_t)rl * C4 + t]);
    float4 v3 = d1 ? v2 : (d2 ? v0 : __ldcg(&xb[(size_t)rtl * C4 + t]));

    __shared__ float salpha[4];
    if (wid == 0) {
#pragma unroll
        for (int off = 16; off > 0; off >>= 1) {
            a.x += __shfl_xor_sync(0xffffffffu, a.x, off);
            a.y += __shfl_xor_sync(0xffffffffu, a.y, off);
            a.z += __shfl_xor_sync(0xffffffffu, a.z, off);
            a.w += __shfl_xor_sync(0xffffffffu, a.w, off);
        }
        if (lane < 4) {
            float comp = (lane == 0) ? a.x : (lane == 1) ? a.y
                       : (lane == 2) ? a.z : a.w;
            salpha[lane] = fmaf(comp, 1.0f / 1024.0f, __ldg(&bias[lane]));
        }
    }
    __syncthreads();
    float c0 = salpha[0], c1 = salpha[1], c2 = salpha[2], c3 = salpha[3];

    float4 w;
    // out[l] = c0 v0 + c1 v1 + c2 v2 + c3 v3
    w.x = fmaf(c0, v0.x, fmaf(c1, v1.x, fmaf(c2, v2.x, c3 * v3.x)));
    w.y = fmaf(c0, v0.y, fmaf(c1, v1.y, fmaf(c2, v2.y, c3 * v3.y)));
    w.z = fmaf(c0, v0.z, fmaf(c1, v1.z, fmaf(c2, v2.z, c3 * v3.z)));
    w.w = fmaf(c0, v0.w, fmaf(c1, v1.w, fmaf(c2, v2.w, c3 * v3.w)));
    __stcs(&ob[(size_t)l * C4 + t], w);

    if (!d1) {  // out[tl] = c0 v1 + c1 v0 + c2 v3 + c3 v2
        w.x = fmaf(c0, v1.x, fmaf(c1, v0.x, fmaf(c2, v3.x, c3 * v2.x)));
        w.y = fmaf(c0, v1.y, fmaf(c1, v0.y, fmaf(c2, v3.y, c3 * v2.y)));
        w.z = fmaf(c0, v1.z, fmaf(c1, v0.z, fmaf(c2, v3.z, c3 * v2.z)));
        w.w = fmaf(c0, v1.w, fmaf(c1, v0.w, fmaf(c2, v3.w, c3 * v2.w)));
        __stcs(&ob[(size_t)tl * C4 + t], w);
    }
    if (!d2) {  // out[rl] = c0 v2 + c1 v3 + c2 v0 + c3 v1
        w.x = fmaf(c0, v2.x, fmaf(c1, v3.x, fmaf(c2, v0.x, c3 * v1.x)));
        w.y = fmaf(c0, v2.y, fmaf(c1, v3.y, fmaf(c2, v0.y, c3 * v1.y)));
        w.z = fmaf(c0, v2.z, fmaf(c1, v3.z, fmaf(c2, v0.z, c3 * v1.z)));
        w.w = fmaf(c0, v2.w, fmaf(c1, v3.w, fmaf(c2, v0.w, c3 * v1.w)));
        __stcs(&ob[(size_t)rl * C4 + t], w);
    }
    if (!d1 && !d2) {  // out[rtl] = c0 v3 + c1 v2 + c2 v1 + c3 v0
        w.x = fmaf(c0, v3.x, fmaf(c1, v2.x, fmaf(c2, v1.x, c3 * v0.x)));
        w.y = fmaf(c0, v3.y, fmaf(c1, v2.y, fmaf(c2, v1.y, c3 * v0.y)));
        w.z = fmaf(c0, v3.z, fmaf(c1, v2.z, fmaf(c2, v1.z, c3 * v0.z)));
        w.w = fmaf(c0, v3.w, fmaf(c1, v2.w, fmaf(c2, v1.w, c3 * v0.w)));
        __stcs(&ob[(size_t)rtl * C4 + t], w);
    }
}

extern "C" void kernel_launch(void* const* d_in, const int* in_sizes, int n_in,
                              void* d_out, int out_size) {
    const float* x    = (const float*)d_in[0];  // (32,1024,768)
    const float* W    = (const float*)d_in[1];  // (4,768)
    const float* bias = (const float*)d_in[2];  // (4,)
    float* out = (float*)d_out;

    dim3 g1(Bn, ZCHUNK);
    pool_kernel<<<g1, 192>>>(x, W);

    // merge with Programmatic Dependent Launch: ramp overlaps the pool tail;
    // every merge block waits (loads nothing) until the pool grid completes.
    cudaLaunchConfig_t cfg = {};
    cfg.gridDim  = dim3(Bn * ORBITS);
    cfg.blockDim = dim3(192);
    cfg.dynamicSmemBytes = 0;
    cfg.stream = 0;
    cudaLaunchAttribute attr[1];
    attr[0].id = cudaLaunchAttributeProgrammaticStreamSerialization;
    attr[0].val.programmaticStreamSerializationAllowed = 1;
    cfg.attrs = attr;
    cfg.numAttrs = 1;
    cudaLaunchKernelEx(&cfg, merge_kernel, x, bias, out);
}